// round 17
// baseline (speedup 1.0000x reference)
#include <cuda_runtime.h>
#include <cstdint>

#define BB 2
#define TT 2048
#define CC 768
#define HH 12
#define NLEFT 6
#define DD 64
#define MM (BB*TT)
#define N1 (3*CC)

#define NEGF (-3.402823466e38f)

// Scratch (device globals: allocation-free)
__device__ float g_q[BB*HH*TT*DD];
__device__ float g_k[BB*HH*TT*DD];
__device__ float g_v[BB*HH*DD*TT];   // TRANSPOSED: [B,H,D,T]
__device__ float g_ctx[BB*TT*CC];
// Pre-rounded (tf32) copies of GEMM inputs
__device__ float g_xr[MM*CC];
__device__ float g_w1r[N1*CC];
__device__ float g_w2r[CC*CC];

__device__ __forceinline__ unsigned f2tf32(float f) {
    unsigned r;
    asm("cvt.rna.tf32.f32 %0, %1;" : "=r"(r) : "f"(f));
    return r;
}
__device__ __forceinline__ float rnd(float f) { return __uint_as_float(f2tf32(f)); }

__device__ __forceinline__ uint32_t smem_u32(const void* p) {
    uint32_t a;
    asm("{ .reg .u64 t; cvta.to.shared.u64 t, %1; cvt.u32.u64 %0, t; }"
        : "=r"(a) : "l"(p));
    return a;
}
__device__ __forceinline__ void cpa16(uint32_t d, const void* s) {
    asm volatile("cp.async.cg.shared.global [%0], [%1], 16;" :: "r"(d), "l"(s));
}
#define CPA_COMMIT() asm volatile("cp.async.commit_group;" ::: "memory")
#define CPA_WAIT(n)  asm volatile("cp.async.wait_group %0;" :: "n"(n) : "memory")

__device__ __forceinline__ void ldsm4(unsigned& r0, unsigned& r1,
                                      unsigned& r2, unsigned& r3, uint32_t addr) {
    asm volatile("ldmatrix.sync.aligned.m8n8.x4.shared.b16 {%0,%1,%2,%3}, [%4];"
                 : "=r"(r0), "=r"(r1), "=r"(r2), "=r"(r3) : "r"(addr));
}
__device__ __forceinline__ void mma8(float* d,
    unsigned a0, unsigned a1, unsigned a2, unsigned a3,
    unsigned b0, unsigned b1)
{
    asm volatile(
        "mma.sync.aligned.m16n8k8.row.col.f32.tf32.tf32.f32 "
        "{%0,%1,%2,%3}, {%4,%5,%6,%7}, {%8,%9}, {%0,%1,%2,%3};"
        : "+f"(d[0]), "+f"(d[1]), "+f"(d[2]), "+f"(d[3])
        : "r"(a0), "r"(a1), "r"(a2), "r"(a3), "r"(b0), "r"(b1));
}

// ---------------------------------------------------------------------------
// Pre-round inputs to tf32 (idempotent wrt all downstream cvt.rna).
// ---------------------------------------------------------------------------
#define XN4  (MM*CC/4)
#define W1N4 (N1*CC/4)
#define W2N4 (CC*CC/4)
#define PRN4 (XN4 + W1N4 + W2N4)

__global__ __launch_bounds__(256) void preround_kernel(
    const float* __restrict__ x, const float* __restrict__ w1,
    const float* __restrict__ w2)
{
    int i = blockIdx.x * 256 + threadIdx.x;
    if (i >= PRN4) return;
    const float* src; float* dst; int j;
    if (i < XN4)              { src = x;  dst = g_xr;  j = i; }
    else if (i < XN4 + W1N4)  { src = w1; dst = g_w1r; j = i - XN4; }
    else                      { src = w2; dst = g_w2r; j = i - XN4 - W1N4; }
    float4 v = *(const float4*)(src + (size_t)j * 4);
    float4 o = make_float4(rnd(v.x), rnd(v.y), rnd(v.z), rnd(v.w));
    *(float4*)(dst + (size_t)j * 4) = o;
}

#define NCH (CC/32)

// ---------------------------------------------------------------------------
// QKV GEMM: 128x128 tile, cp.async pipeline + REGISTER-PIPELINED fragments.
// asm volatile blocks compiler reordering, so LDSM for group g+1/g+2 is
// issued manually BEFORE group g's MMAs (B depth-2, A depth-1).
// V written TRANSPOSED [B,H,D,T].
// ---------------------------------------------------------------------------
#define GW_A   (128*36)
#define W_PR   (2*GW_A)
#define WIDE_SMEM (2 * W_PR * 4)      // 73728 B

__global__ __launch_bounds__(256, 2) void qkv_gemm_kernel(const float* __restrict__ bias)
{
    extern __shared__ unsigned sm[];

    const float* Ag = (const float*)g_xr;
    const float* W  = (const float*)g_w1r;

    const int K = CC;
    const int tid  = threadIdx.x;
    const int lane = tid & 31, warp = tid >> 5;
    const int mw = warp >> 1, nw = warp & 1;
    const int m0 = blockIdx.y * 128, n0 = blockIdx.x * 128;
    const int g = lane >> 2, t = lane & 3;

    const uint32_t smb = smem_u32(sm);

    const int a_row = (lane & 7) + ((lane >> 3) & 1) * 8;
    const int a_ws  = (lane >> 4) * 4;
    const int b_row = (lane & 7) + ((lane >> 4) << 3);
    const int b_ws  = ((lane >> 3) & 1) * 4;

    const uint32_t aad0 = smb + (uint32_t)(((mw * 32 + a_row) * 36 + a_ws) << 2);
    const uint32_t aad1 = aad0 + 16 * 36 * 4;
    uint32_t bad[4];
#pragma unroll
    for (int p = 0; p < 4; p++)
        bad[p] = smb + (uint32_t)((GW_A + (nw * 64 + p * 16 + b_row) * 36 + b_ws) << 2);

    const int lrow = tid >> 3;
    const int lkq  = (tid & 7) << 2;

    float acc[2][8][4];
#pragma unroll
    for (int mt = 0; mt < 2; mt++)
#pragma unroll
        for (int nt = 0; nt < 8; nt++)
#pragma unroll
            for (int c = 0; c < 4; c++) acc[mt][nt][c] = 0.f;

    {
        uint32_t ab = smb, bb = smb + GW_A * 4;
#pragma unroll
        for (int i = 0; i < 4; i++) {
            int row = lrow + i * 32;
            cpa16(ab + (uint32_t)((row * 36 + lkq) << 2),
                  Ag + (size_t)(m0 + row) * K + lkq);
            cpa16(bb + (uint32_t)((row * 36 + lkq) << 2),
                  W + (size_t)(n0 + row) * K + lkq);
        }
        CPA_COMMIT();
    }

    for (int c = 0; c < NCH; c++) {
        const uint32_t bo = (uint32_t)(c & 1) * (W_PR * 4);
        CPA_WAIT(0);
        __syncthreads();
        if (c + 1 < NCH) {
            const int k0n = (c + 1) * 32;
            const uint32_t nbo = (uint32_t)((c + 1) & 1) * (W_PR * 4);
            uint32_t ab = smb + nbo, bb = smb + nbo + GW_A * 4;
#pragma unroll
            for (int i = 0; i < 4; i++) {
                int row = lrow + i * 32;
                cpa16(ab + (uint32_t)((row * 36 + lkq) << 2),
                      Ag + (size_t)(m0 + row) * K + k0n + lkq);
                cpa16(bb + (uint32_t)((row * 36 + lkq) << 2),
                      W + (size_t)(n0 + row) * K + k0n + lkq);
            }
            CPA_COMMIT();
        }

        // Register-pipelined compute: 16 groups (ks 0..3 x p 0..3).
        {
            unsigned aF[2][2][4], bF[3][4];
            ldsm4(aF[0][0][0], aF[0][0][1], aF[0][0][2], aF[0][0][3], aad0 + bo);
            ldsm4(aF[0][1][0], aF[0][1][1], aF[0][1][2], aF[0][1][3], aad1 + bo);
            ldsm4(bF[0][0], bF[0][1], bF[0][2], bF[0][3], bad[0] + bo);
            ldsm4(bF[1][0], bF[1][1], bF[1][2], bF[1][3], bad[1] + bo);
#pragma unroll
            for (int gI = 0; gI < 16; gI++) {
                const int ks = gI >> 2, p = gI & 3;
                if ((gI & 3) == 2 && ks < 3) {      // A depth-1 (2 groups early)
                    const int kn = ks + 1;
                    ldsm4(aF[kn & 1][0][0], aF[kn & 1][0][1],
                          aF[kn & 1][0][2], aF[kn & 1][0][3], aad0 + bo + kn * 32);
                    ldsm4(aF[kn & 1][1][0], aF[kn & 1][1][1],
                          aF[kn & 1][1][2], aF[kn & 1][1][3], aad1 + bo + kn * 32);
                }
                if (gI + 2 < 16) {                  // B depth-2
                    const int gp = gI + 2;
                    ldsm4(bF[gp % 3][0], bF[gp % 3][1],
                          bF[gp % 3][2], bF[gp % 3][3],
                          bad[gp & 3] + bo + (gp >> 2) * 32);
                }
                const unsigned* A0 = aF[ks & 1][0];
                const unsigned* A1 = aF[ks & 1][1];
                const unsigned* Bf = bF[gI % 3];
                mma8(acc[0][2 * p],     A0[0], A0[1], A0[2], A0[3], Bf[0], Bf[1]);
                mma8(acc[0][2 * p + 1], A0[0], A0[1], A0[2], A0[3], Bf[2], Bf[3]);
                mma8(acc[1][2 * p],     A1[0], A1[1], A1[2], A1[3], Bf[0], Bf[1]);
                mma8(acc[1][2 * p + 1], A1[0], A1[1], A1[2], A1[3], Bf[2], Bf[3]);
            }
        }
    }

    const int s  = n0 / CC;
    const int hh = ((n0 % CC) >> 6) + nw;
    if (s == 2) {
        // V: transposed store g_v[(b*HH+hh)*DD + dcol][tok]
#pragma unroll
        for (int mt = 0; mt < 2; mt++) {
            int m = m0 + mw * 32 + mt * 16 + g;
            int b0i = m >> 11, tok0 = m & 2047;
            int m1 = m + 8, b1i = m1 >> 11, tok1 = m1 & 2047;
#pragma unroll
            for (int nt = 0; nt < 8; nt++) {
                int dcol = nt * 8 + t * 2;
                int n = n0 + nw * 64 + dcol;
                float bv0 = bias[n], bv1 = bias[n + 1];
                float v00 = rnd(acc[mt][nt][0] + bv0), v01 = rnd(acc[mt][nt][1] + bv1);
                float v10 = rnd(acc[mt][nt][2] + bv0), v11 = rnd(acc[mt][nt][3] + bv1);
                size_t base0 = ((size_t)(b0i * HH + hh) * DD + dcol) * TT;
                size_t base1 = ((size_t)(b1i * HH + hh) * DD + dcol) * TT;
                g_v[base0 + tok0] = v00;  g_v[base0 + TT + tok0] = v01;
                g_v[base1 + tok1] = v10;  g_v[base1 + TT + tok1] = v11;
            }
        }
    } else {
        float* dst = (s == 0) ? g_q : g_k;
#pragma unroll
        for (int mt = 0; mt < 2; mt++) {
            int m = m0 + mw * 32 + mt * 16 + g;
            int b0i = m >> 11, tok0 = m & 2047;
            int m1 = m + 8, b1i = m1 >> 11, tok1 = m1 & 2047;
#pragma unroll
            for (int nt = 0; nt < 8; nt++) {
                int dcol = nt * 8 + t * 2;
                int n = n0 + nw * 64 + dcol;
                float bv0 = bias[n], bv1 = bias[n + 1];
                float2 r0 = make_float2(rnd(acc[mt][nt][0] + bv0), rnd(acc[mt][nt][1] + bv1));
                float2 r1 = make_float2(rnd(acc[mt][nt][2] + bv0), rnd(acc[mt][nt][3] + bv1));
                *(float2*)(dst + ((size_t)(b0i * HH + hh) * TT + tok0) * DD + dcol) = r0;
                *(float2*)(dst + ((size_t)(b1i * HH + hh) * TT + tok1) * DD + dcol) = r1;
            }
        }
    }
}

// ---------------------------------------------------------------------------
// Out-proj GEMM: 128x64 tile, register-pipelined fragments (depth-1 per ks).
// ---------------------------------------------------------------------------
#define NW_A   (128*36)
#define NW_B   (64*36)
#define NW_PR  (NW_A + NW_B)
#define NARROW_SMEM (2 * NW_PR * 4)   // 55296 B

__global__ __launch_bounds__(256, 2) void out_gemm_kernel(
    const float* __restrict__ bias, float* __restrict__ out)
{
    extern __shared__ unsigned sm[];

    const float* Ag = (const float*)g_ctx;
    const float* W  = (const float*)g_w2r;

    const int K = CC;
    const int tid  = threadIdx.x;
    const int lane = tid & 31, warp = tid >> 5;
    const int mw = warp >> 1, nw = warp & 1;
    const int m0 = blockIdx.y * 128, n0 = blockIdx.x * 64;
    const int g = lane >> 2, t = lane & 3;

    const uint32_t smb = smem_u32(sm);

    const int a_row = (lane & 7) + ((lane >> 3) & 1) * 8;
    const int a_ws  = (lane >> 4) * 4;
    const int b_row = (lane & 7) + ((lane >> 4) << 3);
    const int b_ws  = ((lane >> 3) & 1) * 4;

    const uint32_t aad0 = smb + (uint32_t)(((mw * 32 + a_row) * 36 + a_ws) << 2);
    const uint32_t aad1 = aad0 + 16 * 36 * 4;
    const uint32_t bad0 = smb + (uint32_t)((NW_A + (nw * 32 + b_row) * 36 + b_ws) << 2);
    const uint32_t bad1 = bad0 + 16 * 36 * 4;

    const int lrow = tid >> 3;
    const int lkq  = (tid & 7) << 2;

    float acc[2][4][4];
#pragma unroll
    for (int mt = 0; mt < 2; mt++)
#pragma unroll
        for (int nt = 0; nt < 4; nt++)
#pragma unroll
            for (int c = 0; c < 4; c++) acc[mt][nt][c] = 0.f;

    {
        uint32_t ab = smb, bb = smb + NW_A * 4;
#pragma unroll
        for (int i = 0; i < 4; i++) {
            int row = lrow + i * 32;
            cpa16(ab + (uint32_t)((row * 36 + lkq) << 2),
                  Ag + (size_t)(m0 + row) * K + lkq);
        }
#pragma unroll
        for (int i = 0; i < 2; i++) {
            int row = lrow + i * 32;
            cpa16(bb + (uint32_t)((row * 36 + lkq) << 2),
                  W + (size_t)(n0 + row) * K + lkq);
        }
        CPA_COMMIT();
    }

    for (int c = 0; c < NCH; c++) {
        const uint32_t bo = (uint32_t)(c & 1) * (NW_PR * 4);
        CPA_WAIT(0);
        __syncthreads();
        if (c + 1 < NCH) {
            const int k0n = (c + 1) * 32;
            const uint32_t nbo = (uint32_t)((c + 1) & 1) * (NW_PR * 4);
            uint32_t ab = smb + nbo, bb = smb + nbo + NW_A * 4;
#pragma unroll
            for (int i = 0; i < 4; i++) {
                int row = lrow + i * 32;
                cpa16(ab + (uint32_t)((row * 36 + lkq) << 2),
                      Ag + (size_t)(m0 + row) * K + k0n + lkq);
            }
#pragma unroll
            for (int i = 0; i < 2; i++) {
                int row = lrow + i * 32;
                cpa16(bb + (uint32_t)((row * 36 + lkq) << 2),
                      W + (size_t)(n0 + row) * K + k0n + lkq);
            }
            CPA_COMMIT();
        }

        // Register-pipelined compute: per-ks depth-1.
        {
            unsigned fa0[2][4], fa1[2][4], fba[2][4], fbb[2][4];
            ldsm4(fa0[0][0], fa0[0][1], fa0[0][2], fa0[0][3], aad0 + bo);
            ldsm4(fa1[0][0], fa1[0][1], fa1[0][2], fa1[0][3], aad1 + bo);
            ldsm4(fba[0][0], fba[0][1], fba[0][2], fba[0][3], bad0 + bo);
            ldsm4(fbb[0][0], fbb[0][1], fbb[0][2], fbb[0][3], bad1 + bo);
#pragma unroll
            for (int ks = 0; ks < 4; ks++) {
                if (ks < 3) {
                    const uint32_t kn = bo + (ks + 1) * 32;
                    const int nb = (ks + 1) & 1;
                    ldsm4(fa0[nb][0], fa0[nb][1], fa0[nb][2], fa0[nb][3], aad0 + kn);
                    ldsm4(fa1[nb][0], fa1[nb][1], fa1[nb][2], fa1[nb][3], aad1 + kn);
                    ldsm4(fba[nb][0], fba[nb][1], fba[nb][2], fba[nb][3], bad0 + kn);
                    ldsm4(fbb[nb][0], fbb[nb][1], fbb[nb][2], fbb[nb][3], bad1 + kn);
                }
                const int cb = ks & 1;
                const unsigned* a0 = fa0[cb];
                const unsigned* a1 = fa1[cb];
                const unsigned* bA = fba[cb];
                const unsigned* bBr = fbb[cb];
                mma8(acc[0][0], a0[0], a0[1], a0[2], a0[3], bA[0], bA[1]);
                mma8(acc[0][1], a0[0], a0[1], a0[2], a0[3], bA[2], bA[3]);
                mma8(acc[0][2], a0[0], a0[1], a0[2], a0[3], bBr[0], bBr[1]);
                mma8(acc[0][3], a0[0], a0[1], a0[2], a0[3], bBr[2], bBr[3]);
                mma8(acc[1][0], a1[0], a1[1], a1[2], a1[3], bA[0], bA[1]);
                mma8(acc[1][1], a1[0], a1[1], a1[2], a1[3], bA[2], bA[3]);
                mma8(acc[1][2], a1[0], a1[1], a1[2], a1[3], bBr[0], bBr[1]);
                mma8(acc[1][3], a1[0], a1[1], a1[2], a1[3], bBr[2], bBr[3]);
            }
        }
    }

#pragma unroll
    for (int mt = 0; mt < 2; mt++) {
        int m = m0 + mw * 32 + mt * 16 + g;
#pragma unroll
        for (int nt = 0; nt < 4; nt++) {
            int n = n0 + nw * 32 + nt * 8 + t * 2;
            float bv0 = bias[n], bv1 = bias[n + 1];
            float2 r0 = make_float2(acc[mt][nt][0] + bv0, acc[mt][nt][1] + bv1);
            float2 r1 = make_float2(acc[mt][nt][2] + bv0, acc[mt][nt][3] + bv1);
            *(float2*)(out + (size_t)m * CC + n) = r0;
            *(float2*)(out + (size_t)(m + 8) * CC + n) = r1;
        }
    }
}

// ---------------------------------------------------------------------------
// tf32 MMA flash attention (R16-proven, unchanged): k-split warp pairs,
// single barrier per k-block, cp.async K/V (V transposed), persistent Q frags.
// ---------------------------------------------------------------------------
#define AQ   0
#define AK0  4352
#define AV0  8704
#define AK1  13056
#define AV1  17408
#define APS  21760
#define APM  26112
#define ATTN_SMEM ((28160) * 4)

__global__ __launch_bounds__(256) void attn_mma_kernel(const int* __restrict__ amask)
{
    extern __shared__ unsigned smu[];
    unsigned* Qs = smu + AQ;
    unsigned* Ps = smu + APS;
    float*    pmall = (float*)(smu + APM);

    const int bh = blockIdx.x;
    const int b = bh / HH, h = bh % HH;
    const bool left = (h < NLEFT);
    const int qb = left ? (TT / 64 - 1 - blockIdx.y) : blockIdx.y;   // LPT

    const float* Qg = g_q + (size_t)bh * TT * DD;
    const float* Kg = g_k + (size_t)bh * TT * DD;
    const float* Vg = g_v + (size_t)bh * DD * TT;     // [D][T]

    const int tid = threadIdx.x;
    const int lane = tid & 31, warp = tid >> 5;
    const int g = lane >> 2, t = lane & 3;
    const int qgrp = warp & 3, kh = warp >> 2;
    const int rm = qgrp * 16;
    const int kc0 = kh * 32;

    const int a_row = (lane & 7) + ((lane >> 3) & 1) * 8;
    const int a_ws  = (lane >> 4) * 4;
    const int b_row = (lane & 7) + ((lane >> 4) << 3);
    const int b_ws  = ((lane >> 3) & 1) * 4;

    const uint32_t smb = smem_u32(smu);
    const uint32_t qad  = smb + (uint32_t)(((rm + a_row) * 68 + a_ws + AQ)  << 2);
    const uint32_t padr = smb + (uint32_t)(((rm + a_row) * 68 + kc0 + a_ws + APS) << 2);
    uint32_t kad[2];
#pragma unroll
    for (int p = 0; p < 2; p++)
        kad[p] = smb + (uint32_t)((AK0 + (kc0 + p * 16 + b_row) * 68 + b_ws) << 2);
    uint32_t vad[4];
#pragma unroll
    for (int p = 0; p < 4; p++)
        vad[p] = smb + (uint32_t)((AV0 + (p * 16 + b_row) * 68 + kc0 + b_ws) << 2);

    const int lrow0 = tid >> 4;
    const int ld4   = (tid & 15) << 2;

    // Q load (scaled by 1/8, exact; inputs already tf32-rounded)
#pragma unroll
    for (int i = 0; i < 4; i++) {
        int row = lrow0 + i * 16;
        float4 v = *(const float4*)(Qg + (size_t)(qb * 64 + row) * DD + ld4);
        Qs[row * 68 + ld4 + 0] = f2tf32(v.x * 0.125f);
        Qs[row * 68 + ld4 + 1] = f2tf32(v.y * 0.125f);
        Qs[row * 68 + ld4 + 2] = f2tf32(v.z * 0.125f);
        Qs[row * 68 + ld4 + 3] = f2tf32(v.w * 0.125f);
    }
#pragma unroll
    for (int i = 0; i < 8; i++) {
        int idx = tid + i * 256;
        pmall[idx] = amask[b * TT + idx] ? 0.f : NEGF;
    }

    const int kb0 = left ? 0 : qb;
    const int kb1 = left ? qb : (TT / 64 - 1);
    const int qi0 = qb * 64 + rm + g, qi1 = qi0 + 8;
    const bool skipdiag = left ? (kh == 1 && rm < 32) : (kh == 0 && rm >= 32);

    {   // prologue: prefetch kb0 into buffer 0 (K rows = kseq; Vt rows = d)
        const float* Kp = Kg + (size_t)kb0 * 64 * DD;
        uint32_t kb_ = smb + AK0 * 4, vb_ = smb + AV0 * 4;
#pragma unroll
        for (int i = 0; i < 4; i++) {
            int row = lrow0 + i * 16;
            uint32_t off = (uint32_t)((row * 68 + ld4) << 2);
            cpa16(kb_ + off, Kp + row * DD + ld4);
            cpa16(vb_ + off, Vg + (size_t)row * TT + kb0 * 64 + ld4);
        }
        CPA_COMMIT();
    }

    __syncthreads();                     // Q tile complete
    unsigned qa[8][4];                   // persistent Q fragments
#pragma unroll
    for (int ks = 0; ks < 8; ks++)
        ldsm4(qa[ks][0], qa[ks][1], qa[ks][2], qa[ks][3], qad + ks * 32);

    float m_r[2] = {NEGF, NEGF};
    float l_r[2] = {0.f, 0.f};
    float O[8][4];
#pragma unroll
    for (int nt = 0; nt < 8; nt++)
#pragma unroll
        for (int c = 0; c < 4; c++) O[nt][c] = 0.f;

    for (int kb = kb0, it = 0; kb <= kb1; kb++, it++) {
        const int buf = it & 1;
        const uint32_t bufoff = (uint32_t)buf * ((AK1 - AK0) * 4);
        CPA_WAIT(0);
        __syncthreads();                 // kb visible; other buffer free
        if (kb + 1 <= kb1) {
            const float* Kp = Kg + (size_t)(kb + 1) * 64 * DD;
            const uint32_t nbo = (uint32_t)(buf ^ 1) * ((AK1 - AK0) * 4);
            uint32_t kb_ = smb + AK0 * 4 + nbo, vb_ = smb + AV0 * 4 + nbo;
#pragma unroll
            for (int i = 0; i < 4; i++) {
                int row = lrow0 + i * 16;
                uint32_t off = (uint32_t)((row * 68 + ld4) << 2);
                cpa16(kb_ + off, Kp + row * DD + ld4);
                cpa16(vb_ + off, Vg + (size_t)row * TT + (kb + 1) * 64 + ld4);
            }
            CPA_COMMIT();
        }

        const bool diag = (kb == qb);
        if (diag && skipdiag) continue;  // prefetch already issued; safe

        // S = Q @ K^T  (warp: 16 rows x its 32 cols); Q frags from registers
        float S[4][4];
#pragma unroll
        for (int nt = 0; nt < 4; nt++)
#pragma unroll
            for (int c = 0; c < 4; c++) S[nt][c] = 0.f;

#pragma unroll
        for (int ks = 0; ks < 8; ks++) {
            const uint32_t ko = ks * 32;
#pragma unroll
            for (int p = 0; p < 2; p++) {
                unsigned k0, k1, k2, k3;
                ldsm4(k0, k1, k2, k3, kad[p] + bufoff + ko);
                mma8(S[2 * p],     qa[ks][0], qa[ks][1], qa[ks][2], qa[ks][3], k0, k1);
                mma8(S[2 * p + 1], qa[ks][0], qa[ks][1], qa[ks][2], qa[ks][3], k2, k3);
            }
        }

        // Mask + online softmax over this warp's 32 cols
        float mx0 = NEGF, mx1 = NEGF;
        const int kbase = kb * 64;
#pragma unroll
        for (int nt = 0; nt < 4; nt++) {
            int c0 = kc0 + nt * 8 + t * 2;
            float p0 = pmall[kbase + c0], p1 = pmall[kbase + c0 + 1];
            float s0 = S[nt][0] + p0, s1 = S[nt][1] + p1;
            float s2 = S[nt][2] + p0, s3 = S[nt][3] + p1;
            if (diag) {
                int k0i = kbase + c0, k1i = k0i + 1;
                if (left) {
                    if (k0i > qi0) s0 = NEGF;
                    if (k1i > qi0) s1 = NEGF;
                    if (k0i > qi1) s2 = NEGF;
                    if (k1i > qi1) s3 = NEGF;
                } else {
                    if (k0i < qi0) s0 = NEGF;
                    if (k1i < qi0) s1 = NEGF;
                    if (k0i < qi1) s2 = NEGF;
                    if (k1i < qi1) s3 = NEGF;
                }
            }
            S[nt][0] = s0; S[nt][1] = s1; S[nt][2] = s2; S[nt][3] = s3;
            mx0 = fmaxf(mx0, fmaxf(s0, s1));
            mx1 = fmaxf(mx1, fmaxf(s2, s3));
        }
        mx0 = fmaxf(mx0, __shfl_xor_sync(0xffffffffu, mx0, 1));
        mx0 = fmaxf(mx0, __shfl_xor_sync(0xffffffffu, mx0, 2));
        mx1 = fmaxf(mx1, __shfl_xor_sync(0xffffffffu, mx1, 1));
        mx1 = fmaxf(mx1, __shfl_xor_sync(0xffffffffu, mx1, 2));

        float mn0 = fmaxf(m_r[0], mx0), mn1 = fmaxf(m_r[1], mx1);
        float al0 = __expf(m_r[0] - mn0), al1 = __expf(m_r[1] - mn1);
        m_r[0] = mn0; m_r[1] = mn1;

        float rs0 = 0.f, rs1 = 0.f;
#pragma unroll
        for (int nt = 0; nt < 4; nt++) {
            float e0 = __expf(S[nt][0] - mn0), e1 = __expf(S[nt][1] - mn0);
            float e2 = __expf(S[nt][2] - mn1), e3 = __expf(S[nt][3] - mn1);
            S[nt][0] = e0; S[nt][1] = e1; S[nt][2] = e2; S[nt][3] = e3;
            rs0 += e0 + e1; rs1 += e2 + e3;
        }
        rs0 += __shfl_xor_sync(0xffffffffu, rs0, 1);
        rs0 += __shfl_xor_sync(0xffffffffu, rs0, 2);
        rs1 += __shfl_xor_sync(0xffffffffu, rs1, 1);
        rs1 += __shfl_xor_sync(0xffffffffu, rs1, 2);
        l_r[0] = l_r[0] * al0 + rs0;
        l_r[1] = l_r[1] * al1 + rs1;
#pragma unroll
        for (int nt = 0; nt < 8; nt++) {
            O[nt][0] *= al0; O[nt][1] *= al0;
            O[nt][2] *= al1; O[nt][3] *= al1;
        }

        // P -> smem (warp-private rows x warp-private cols)
        __syncwarp();
#pragma unroll
        for (int nt = 0; nt < 4; nt++) {
            int c0 = kc0 + nt * 8 + t * 2;
            Ps[(rm     + g) * 68 + c0    ] = f2tf32(S[nt][0]);
            Ps[(rm     + g) * 68 + c0 + 1] = f2tf32(S[nt][1]);
            Ps[(rm + 8 + g) * 68 + c0    ] = f2tf32(S[nt][2]);
            Ps[(rm + 8 + g) * 68 + c0 + 1] = f2tf32(S[nt][3]);
        }
        __syncwarp();

        // O += P(16 x its 32) @ Vt^T : b-frags via ldmatrix on Vt rows
#pragma unroll
        for (int ks = 0; ks < 4; ks++) {
            const uint32_t ko = ks * 32;
            unsigned a0, a1, a2, a3;
            ldsm4(a0, a1, a2, a3, padr + ko);
#pragma unroll
            for (int p = 0; p < 4; p++) {
                unsigned bf[4];
                ldsm4(bf[0], bf[1], bf[2], bf[3], vad[p] + bufoff + ko);
                mma8(O[2*p],   a0, a1, a2, a3, bf[0], bf[1]);
                mma8(O[2*p+1], a0, a1, a2, a3, bf[2], bf[3]);
            }
        }
    }

    // ----- Merge warp pair (kh=0 <- kh=1) and write ctx -----
    __syncthreads();                     // all compute done; Ps/pm dead
    float* sc = (float*)(smu + APS);     // scratch [4 warps][32 lanes][37]
    if (kh == 1) {
        int base = (qgrp * 32 + lane) * 37;
#pragma unroll
        for (int nt = 0; nt < 8; nt++) {
            sc[base + nt * 4 + 0] = O[nt][0];
            sc[base + nt * 4 + 1] = O[nt][1];
            sc[base + nt * 4 + 2] = O[nt][2];
            sc[base + nt * 4 + 3] = O[nt][3];
        }
        sc[base + 32] = m_r[0]; sc[base + 33] = m_r[1];
        sc[base + 34] = l_r[0]; sc[base + 35] = l_r[1];
    }
    __syncthreads();
    if (kh == 0) {
        int base = (qgrp * 32 + lane) * 37;
        float mb0 = sc[base + 32], mb1 = sc[base + 33];
        float lb0 = sc[base + 34], lb1 = sc[base + 35];
        float M0 = fmaxf(m_r[0], mb0), M1 = fmaxf(m_r[1], mb1);
        float sa0 = __expf(m_r[0] - M0), sb0 = __expf(mb0 - M0);
        float sa1 = __expf(m_r[1] - M1), sb1 = __expf(mb1 - M1);
        float L0 = l_r[0] * sa0 + lb0 * sb0;
        float L1 = l_r[1] * sa1 + lb1 * sb1;
        float inv0 = 1.0f / L0, inv1 = 1.0f / L1;
        int t0 = qb * 64 + rm + g, t1 = t0 + 8;
#pragma unroll
        for (int nt = 0; nt < 8; nt++) {
            float o0 = O[nt][0] * sa0 + sc[base + nt * 4 + 0] * sb0;
            float o1 = O[nt][1] * sa0 + sc[base + nt * 4 + 1] * sb0;
            float o2 = O[nt][2] * sa1 + sc[base + nt * 4 + 2] * sb1;
            float o3 = O[nt][3] * sa1 + sc[base + nt * 4 + 3] * sb1;
            int col = h * DD + nt * 8 + t * 2;
            *(float2*)(g_ctx + ((size_t)b * TT + t0) * CC + col) =
                make_float2(rnd(o0 * inv0), rnd(o1 * inv0));
            *(float2*)(g_ctx + ((size_t)b * TT + t1) * CC + col) =
                make_float2(rnd(o2 * inv1), rnd(o3 * inv1));
        }
    }
}

// ---------------------------------------------------------------------------
extern "C" void kernel_launch(void* const* d_in, const int* in_sizes, int n_in,
                              void* d_out, int out_size)
{
    const float* x      = (const float*)d_in[0];
    const int*   amask  = (const int*)  d_in[1];
    const float* Wqkv_w = (const float*)d_in[2];
    const float* Wqkv_b = (const float*)d_in[3];
    const float* Wo_w   = (const float*)d_in[4];
    const float* Wo_b   = (const float*)d_in[5];
    float* out = (float*)d_out;

    (void)in_sizes; (void)n_in; (void)out_size;

    cudaFuncSetAttribute(attn_mma_kernel,
                         cudaFuncAttributeMaxDynamicSharedMemorySize, ATTN_SMEM);
    cudaFuncSetAttribute(qkv_gemm_kernel,
                         cudaFuncAttributeMaxDynamicSharedMemorySize, WIDE_SMEM);
    cudaFuncSetAttribute(out_gemm_kernel,
                         cudaFuncAttributeMaxDynamicSharedMemorySize, NARROW_SMEM);

    preround_kernel<<<(PRN4 + 255) / 256, 256>>>(x, Wqkv_w, Wo_w);
    qkv_gemm_kernel<<<dim3(N1 / 128, MM / 128), 256, WIDE_SMEM>>>(Wqkv_b);
    attn_mma_kernel<<<dim3(BB * HH, TT / 64), 256, ATTN_SMEM>>>(amask);
    out_gemm_kernel<<<dim3(CC / 64, MM / 128), 256, NARROW_SMEM>>>(Wo_b, out);
}